// round 1
// baseline (speedup 1.0000x reference)
#include <cuda_runtime.h>

#define NMAX   50000
#define EMAX   800000
#define H      96
#define CIN    128
#define COUT   40
#define NLAYER 5
#define DTC    0.05f

// ---------------- device scratch (static, no allocs) ----------------
__device__ int   g_deg[NMAX];
__device__ int   g_rowptr[NMAX + 1];
__device__ int   g_cursor[NMAX];
__device__ float g_deginv[NMAX];
__device__ int   g_srcs[EMAX];
__device__ float g_X0[(size_t)NMAX * H];
__device__ float g_Y0[(size_t)NMAX * H];
__device__ float g_X1[(size_t)NMAX * H];
__device__ float g_Y1[(size_t)NMAX * H];

// ---------------- CSR build ----------------
__global__ void k_deg(const int* __restrict__ dst, int E) {
    int e = blockIdx.x * blockDim.x + threadIdx.x;
    if (e < E) atomicAdd(&g_deg[dst[e]], 1);
}

__global__ void k_scan(int N) {
    __shared__ int sm[1024];
    int tid = threadIdx.x;
    int per = (N + 1023) >> 10;
    int b = tid * per;
    int e = b + per; if (e > N) e = N; if (b > N) b = N;
    int sum = 0;
    for (int i = b; i < e; ++i) sum += g_deg[i];
    sm[tid] = sum;
    __syncthreads();
    // inclusive Hillis-Steele scan over 1024 partials
    for (int off = 1; off < 1024; off <<= 1) {
        int v = 0;
        if (tid >= off) v = sm[tid - off];
        __syncthreads();
        sm[tid] += v;
        __syncthreads();
    }
    int run = sm[tid] - sum;  // exclusive prefix
    for (int i = b; i < e; ++i) {
        int dg = g_deg[i];
        g_rowptr[i] = run;
        g_cursor[i] = run;
        g_deginv[i] = 1.0f / (float)(dg > 1 ? dg : 1);
        run += dg;
    }
    if (tid == 0) g_rowptr[N] = sm[1023];
}

__global__ void k_scatter(const int* __restrict__ src, const int* __restrict__ dst, int E) {
    int e = blockIdx.x * blockDim.x + threadIdx.x;
    if (e < E) {
        int p = atomicAdd(&g_cursor[dst[e]], 1);
        g_srcs[p] = src[e];
    }
}

// ---------------- lift: X = tanh(x@Wx+bx), Y = tanh(x@Wy+by) ----------------
// Treat as C[N x 192] = x[N x 128] @ [Wx | Wy]. 128 threads/block,
// block tile 128 rows x 64 cols (gridDim.y = 3 col-blocks), thread tile 8x8.
__global__ void k_lift(const float* __restrict__ x,
                       const float* __restrict__ Wx, const float* __restrict__ bx,
                       const float* __restrict__ Wy, const float* __restrict__ by,
                       int N) {
    __shared__ float xs[128][33];
    __shared__ float ws[32][64];
    int tid = threadIdx.x;
    int tx = tid & 7;        // col group (8)
    int ty = tid >> 3;       // row group (16)
    int cb = blockIdx.y;     // 0..2
    int row0 = blockIdx.x * 128;

    float acc[8][8];
#pragma unroll
    for (int i = 0; i < 8; ++i)
#pragma unroll
        for (int j = 0; j < 8; ++j) acc[i][j] = 0.f;

    for (int kt = 0; kt < CIN; kt += 32) {
        // load x tile (128 x 32) via float4
#pragma unroll
        for (int j = 0; j < 8; ++j) {
            int f4 = tid + j * 128;
            int r = f4 >> 3;
            int kq = f4 & 7;
            float4 v = make_float4(0.f, 0.f, 0.f, 0.f);
            int gr = row0 + r;
            if (gr < N) v = *(const float4*)(x + (size_t)gr * CIN + kt + kq * 4);
            xs[r][kq * 4 + 0] = v.x; xs[r][kq * 4 + 1] = v.y;
            xs[r][kq * 4 + 2] = v.z; xs[r][kq * 4 + 3] = v.w;
        }
        // load W tile (32 x 64) of virtual [Wx|Wy]
#pragma unroll
        for (int j = 0; j < 16; ++j) {
            int idx = tid + j * 128;   // 0..2047
            int k = idx >> 6;
            int c = idx & 63;
            int gc = cb * 64 + c;
            int gk = kt + k;
            float w = (gc < H) ? Wx[gk * H + gc] : Wy[gk * H + (gc - H)];
            ws[k][c] = w;
        }
        __syncthreads();
#pragma unroll
        for (int k = 0; k < 32; ++k) {
            float xv[8];
#pragma unroll
            for (int i = 0; i < 8; ++i) xv[i] = xs[ty * 8 + i][k];
            float4 w0 = *(float4*)&ws[k][tx * 8];
            float4 w1 = *(float4*)&ws[k][tx * 8 + 4];
            float wv[8] = {w0.x, w0.y, w0.z, w0.w, w1.x, w1.y, w1.z, w1.w};
#pragma unroll
            for (int i = 0; i < 8; ++i)
#pragma unroll
                for (int j = 0; j < 8; ++j) acc[i][j] += xv[i] * wv[j];
        }
        __syncthreads();
    }
    // epilogue: tanh(acc + bias) -> g_X0 / g_Y0. Each thread's 8-col chunk
    // lies entirely in one of Wx/Wy (chunks of 8, boundary at 96).
    int c0 = cb * 64 + tx * 8;
    bool isX = (c0 < H);
    int cc0 = isX ? c0 : (c0 - H);
    float bb[8];
#pragma unroll
    for (int j = 0; j < 8; ++j) bb[j] = isX ? bx[cc0 + j] : by[cc0 + j];
    float* outp = isX ? g_X0 : g_Y0;
#pragma unroll
    for (int i = 0; i < 8; ++i) {
        int gr = row0 + ty * 8 + i;
        if (gr < N) {
#pragma unroll
            for (int j = 0; j < 8; ++j)
                outp[(size_t)gr * H + cc0 + j] = tanhf(acc[i][j] + bb[j]);
        }
    }
}

// ---------------- one LVConv layer: gather mean + explicit Euler ----------------
// warp per dst node; 96 channels = 3 per lane.
__global__ void k_layer(const float* __restrict__ Xin, const float* __restrict__ Yin,
                        float* __restrict__ Xout, float* __restrict__ Yout,
                        const float* __restrict__ al, const float* __restrict__ be,
                        const float* __restrict__ ga, const float* __restrict__ de,
                        int N) {
    int w = (blockIdx.x * blockDim.x + threadIdx.x) >> 5;
    int lane = threadIdx.x & 31;
    if (w >= N) return;
    int s0 = g_rowptr[w];
    int s1 = g_rowptr[w + 1];
    float ax0 = 0.f, ax1 = 0.f, ax2 = 0.f;
    float ay0 = 0.f, ay1 = 0.f, ay2 = 0.f;
    for (int e = s0; e < s1; ++e) {
        int s = __ldg(&g_srcs[e]);
        const float* xp = Xin + (size_t)s * H;
        const float* yp = Yin + (size_t)s * H;
        ax0 += __ldg(xp + lane);      ay0 += __ldg(yp + lane);
        ax1 += __ldg(xp + lane + 32); ay1 += __ldg(yp + lane + 32);
        ax2 += __ldg(xp + lane + 64); ay2 += __ldg(yp + lane + 64);
    }
    float dinv = g_deginv[w];
    float aggx[3] = {ax0 * dinv, ax1 * dinv, ax2 * dinv};
    float aggy[3] = {ay0 * dinv, ay1 * dinv, ay2 * dinv};
    size_t base = (size_t)w * H;
#pragma unroll
    for (int j = 0; j < 3; ++j) {
        int c = lane + 32 * j;
        float Xv = Xin[base + c];
        float Yv = Yin[base + c];
        Xout[base + c] = Xv + DTC * Xv * (al[c] - be[c] * aggy[j]);
        Yout[base + c] = Yv + DTC * Yv * (-ga[c] + de[c] * aggx[j]);
    }
}

// ---------------- readout: out = [X|Y] @ Wr + br ----------------
// 128 threads/block, 128 rows/block, thread tile 8 rows x 5 cols (40 cols).
__global__ void k_readout(const float* __restrict__ Xf, const float* __restrict__ Yf,
                          const float* __restrict__ Wr, const float* __restrict__ br,
                          float* __restrict__ out, int N) {
    __shared__ float xs[128][33];
    __shared__ float ws[32][COUT];
    int tid = threadIdx.x;
    int tx = tid & 7;
    int ty = tid >> 3;
    int row0 = blockIdx.x * 128;
    float acc[8][5];
#pragma unroll
    for (int i = 0; i < 8; ++i)
#pragma unroll
        for (int j = 0; j < 5; ++j) acc[i][j] = 0.f;

    for (int kt = 0; kt < 2 * H; kt += 32) {
        const float* srcm = (kt < H) ? Xf : Yf;
        int kof = (kt < H) ? kt : (kt - H);
#pragma unroll
        for (int j = 0; j < 8; ++j) {
            int f4 = tid + j * 128;
            int r = f4 >> 3;
            int kq = f4 & 7;
            float4 v = make_float4(0.f, 0.f, 0.f, 0.f);
            int gr = row0 + r;
            if (gr < N) v = *(const float4*)(srcm + (size_t)gr * H + kof + kq * 4);
            xs[r][kq * 4 + 0] = v.x; xs[r][kq * 4 + 1] = v.y;
            xs[r][kq * 4 + 2] = v.z; xs[r][kq * 4 + 3] = v.w;
        }
#pragma unroll
        for (int j = 0; j < 10; ++j) {
            int idx = tid + j * 128;   // 0..1279
            if (idx < 32 * COUT) {
                int k = idx / COUT;
                int c = idx - k * COUT;
                ws[k][c] = Wr[(size_t)(kt + k) * COUT + c];
            }
        }
        __syncthreads();
#pragma unroll
        for (int k = 0; k < 32; ++k) {
            float xv[8];
#pragma unroll
            for (int i = 0; i < 8; ++i) xv[i] = xs[ty * 8 + i][k];
            float wv[5];
#pragma unroll
            for (int j = 0; j < 5; ++j) wv[j] = ws[k][tx * 5 + j];
#pragma unroll
            for (int i = 0; i < 8; ++i)
#pragma unroll
                for (int j = 0; j < 5; ++j) acc[i][j] += xv[i] * wv[j];
        }
        __syncthreads();
    }
#pragma unroll
    for (int i = 0; i < 8; ++i) {
        int gr = row0 + ty * 8 + i;
        if (gr < N) {
#pragma unroll
            for (int j = 0; j < 5; ++j)
                out[(size_t)gr * COUT + tx * 5 + j] = acc[i][j] + br[tx * 5 + j];
        }
    }
}

// ---------------- launch ----------------
extern "C" void kernel_launch(void* const* d_in, const int* in_sizes, int n_in,
                              void* d_out, int out_size) {
    const float* x  = (const float*)d_in[0];
    const int*   ei = (const int*)d_in[1];
    const float* Wx = (const float*)d_in[2];
    const float* bx = (const float*)d_in[3];
    const float* Wy = (const float*)d_in[4];
    const float* by = (const float*)d_in[5];
    const float* al = (const float*)d_in[6];
    const float* be = (const float*)d_in[7];
    const float* ga = (const float*)d_in[8];
    const float* de = (const float*)d_in[9];
    const float* Wr = (const float*)d_in[10];
    const float* br = (const float*)d_in[11];
    float* out = (float*)d_out;

    int N = in_sizes[0] / CIN;
    int E = in_sizes[1] / 2;
    if (N > NMAX) N = NMAX;
    if (E > EMAX) E = EMAX;
    const int* srcp = ei;
    const int* dstp = ei + E;

    void* degp;
    cudaGetSymbolAddress(&degp, g_deg);
    cudaMemsetAsync(degp, 0, (size_t)N * sizeof(int));

    k_deg<<<(E + 255) / 256, 256>>>(dstp, E);
    k_scan<<<1, 1024>>>(N);
    k_scatter<<<(E + 255) / 256, 256>>>(srcp, dstp, E);

    dim3 gl((N + 127) / 128, 3);
    k_lift<<<gl, 128>>>(x, Wx, bx, Wy, by, N);

    float* Xb[2];
    float* Yb[2];
    cudaGetSymbolAddress((void**)&Xb[0], g_X0);
    cudaGetSymbolAddress((void**)&Yb[0], g_Y0);
    cudaGetSymbolAddress((void**)&Xb[1], g_X1);
    cudaGetSymbolAddress((void**)&Yb[1], g_Y1);

    int nwarps = N;
    int layerBlocks = (nwarps * 32 + 255) / 256;
    for (int l = 0; l < NLAYER; ++l) {
        k_layer<<<layerBlocks, 256>>>(Xb[l & 1], Yb[l & 1],
                                      Xb[(l + 1) & 1], Yb[(l + 1) & 1],
                                      al + l * H, be + l * H, ga + l * H, de + l * H, N);
    }
    k_readout<<<(N + 127) / 128, 128>>>(Xb[NLAYER & 1], Yb[NLAYER & 1], Wr, br, out, N);
}

// round 2
// speedup vs baseline: 1.0546x; 1.0546x over previous
#include <cuda_runtime.h>
#include <cuda_fp16.h>

#define NMAX   50000
#define EMAX   800000
#define H      96
#define CIN    128
#define COUT   40
#define NLAYER 5
#define DTC    0.05f

// ---------------- device scratch (static, no allocs) ----------------
__device__ int   g_deg[NMAX];
__device__ int   g_rowptr[NMAX + 1];
__device__ int   g_cursor[NMAX];
__device__ float g_deginv[NMAX];
__device__ int   g_srcs[EMAX];
__device__ float g_X0[(size_t)NMAX * H];
__device__ float g_Y0[(size_t)NMAX * H];
__device__ float g_X1[(size_t)NMAX * H];
__device__ float g_Y1[(size_t)NMAX * H];
__device__ __half2 g_XY0[(size_t)NMAX * H];   // interleaved (X,Y) per channel, fp16
__device__ __half2 g_XY1[(size_t)NMAX * H];

// ---------------- f32x2 packed-FMA helpers ----------------
__device__ __forceinline__ unsigned long long pack2(float v) {
    unsigned long long r; unsigned int u = __float_as_uint(v);
    asm("mov.b64 %0, {%1, %1};" : "=l"(r) : "r"(u));
    return r;
}
__device__ __forceinline__ void unpack2(unsigned long long v, float& a, float& b) {
    unsigned int x, y;
    asm("mov.b64 {%0, %1}, %2;" : "=r"(x), "=r"(y) : "l"(v));
    a = __uint_as_float(x); b = __uint_as_float(y);
}
__device__ __forceinline__ void ffma2(unsigned long long& d,
                                      unsigned long long a, unsigned long long b) {
    asm("fma.rn.f32x2 %0, %1, %2, %0;" : "+l"(d) : "l"(a), "l"(b));
}

// ---------------- CSR build ----------------
__global__ void k_deg(const int* __restrict__ dst, int E) {
    int e = blockIdx.x * blockDim.x + threadIdx.x;
    if (e < E) atomicAdd(&g_deg[dst[e]], 1);
}

__global__ void k_scan(int N) {
    __shared__ int sm[1024];
    int tid = threadIdx.x;
    int per = (N + 1023) >> 10;
    int b = tid * per;
    int e = b + per; if (e > N) e = N; if (b > N) b = N;
    int sum = 0;
    for (int i = b; i < e; ++i) sum += g_deg[i];
    sm[tid] = sum;
    __syncthreads();
    for (int off = 1; off < 1024; off <<= 1) {
        int v = 0;
        if (tid >= off) v = sm[tid - off];
        __syncthreads();
        sm[tid] += v;
        __syncthreads();
    }
    int run = sm[tid] - sum;  // exclusive prefix
    for (int i = b; i < e; ++i) {
        int dg = g_deg[i];
        g_rowptr[i] = run;
        g_cursor[i] = run;
        g_deginv[i] = 1.0f / (float)(dg > 1 ? dg : 1);
        run += dg;
    }
    if (tid == 0) g_rowptr[N] = sm[1023];
}

__global__ void k_scatter(const int* __restrict__ src, const int* __restrict__ dst, int E) {
    int e = blockIdx.x * blockDim.x + threadIdx.x;
    if (e < E) {
        int p = atomicAdd(&g_cursor[dst[e]], 1);
        g_srcs[p] = src[e];
    }
}

// ---------------- lift: X = tanh(x@Wx+bx), Y = tanh(x@Wy+by) ----------------
// C[N x 192] = x[N x 128] @ [Wx | Wy]. 128 threads/block, block tile 128x64,
// thread tile 8x8 with packed f32x2 FMA (4 packed col-pairs).
__global__ void k_lift(const float* __restrict__ x,
                       const float* __restrict__ Wx, const float* __restrict__ bx,
                       const float* __restrict__ Wy, const float* __restrict__ by,
                       int N) {
    __shared__ __align__(16) float xs[128][33];
    __shared__ __align__(16) float ws[32][64];
    int tid = threadIdx.x;
    int tx = tid & 7;        // col group (8)
    int ty = tid >> 3;       // row group (16)
    int cb = blockIdx.y;     // 0..2
    int row0 = blockIdx.x * 128;

    unsigned long long acc[8][4];
#pragma unroll
    for (int i = 0; i < 8; ++i)
#pragma unroll
        for (int j = 0; j < 4; ++j) acc[i][j] = 0ull;

    for (int kt = 0; kt < CIN; kt += 32) {
#pragma unroll
        for (int j = 0; j < 8; ++j) {
            int f4 = tid + j * 128;
            int r = f4 >> 3;
            int kq = f4 & 7;
            float4 v = make_float4(0.f, 0.f, 0.f, 0.f);
            int gr = row0 + r;
            if (gr < N) v = *(const float4*)(x + (size_t)gr * CIN + kt + kq * 4);
            xs[r][kq * 4 + 0] = v.x; xs[r][kq * 4 + 1] = v.y;
            xs[r][kq * 4 + 2] = v.z; xs[r][kq * 4 + 3] = v.w;
        }
#pragma unroll
        for (int j = 0; j < 16; ++j) {
            int idx = tid + j * 128;   // 0..2047
            int k = idx >> 6;
            int c = idx & 63;
            int gc = cb * 64 + c;
            int gk = kt + k;
            float w = (gc < H) ? Wx[gk * H + gc] : Wy[gk * H + (gc - H)];
            ws[k][c] = w;
        }
        __syncthreads();
#pragma unroll
        for (int k = 0; k < 32; ++k) {
            unsigned long long a2[8];
#pragma unroll
            for (int i = 0; i < 8; ++i) a2[i] = pack2(xs[ty * 8 + i][k]);
            const unsigned long long* wp =
                reinterpret_cast<const unsigned long long*>(&ws[k][tx * 8]);
            unsigned long long b0 = wp[0], b1 = wp[1], b2 = wp[2], b3 = wp[3];
#pragma unroll
            for (int i = 0; i < 8; ++i) {
                ffma2(acc[i][0], a2[i], b0);
                ffma2(acc[i][1], a2[i], b1);
                ffma2(acc[i][2], a2[i], b2);
                ffma2(acc[i][3], a2[i], b3);
            }
        }
        __syncthreads();
    }
    // epilogue: tanh(acc + bias) -> g_X0 / g_Y0 (chunks of 8, boundary at 96).
    int c0 = cb * 64 + tx * 8;
    bool isX = (c0 < H);
    int cc0 = isX ? c0 : (c0 - H);
    float bb[8];
#pragma unroll
    for (int j = 0; j < 8; ++j) bb[j] = isX ? bx[cc0 + j] : by[cc0 + j];
    float* outp = isX ? g_X0 : g_Y0;
#pragma unroll
    for (int i = 0; i < 8; ++i) {
        int gr = row0 + ty * 8 + i;
        if (gr < N) {
#pragma unroll
            for (int j = 0; j < 4; ++j) {
                float v0, v1;
                unpack2(acc[i][j], v0, v1);
                outp[(size_t)gr * H + cc0 + 2 * j]     = tanhf(v0 + bb[2 * j]);
                outp[(size_t)gr * H + cc0 + 2 * j + 1] = tanhf(v1 + bb[2 * j + 1]);
            }
        }
    }
}

// ---------------- pack fp32 X,Y -> interleaved half2 XY ----------------
__global__ void k_pack(const float* __restrict__ X, const float* __restrict__ Y,
                       __half2* __restrict__ XY, int total) {
    int i = blockIdx.x * blockDim.x + threadIdx.x;
    if (i < total) XY[i] = __floats2half2_rn(X[i], Y[i]);
}

// ---------------- one LVConv layer ----------------
// warp per dst node; gathers fp16 (X,Y) pairs, updates fp32 state, writes
// fp32 state + half2 copy for the next layer's gather.
__global__ void k_layer(const float* __restrict__ Xin, const float* __restrict__ Yin,
                        const __half2* __restrict__ XYin,
                        float* __restrict__ Xout, float* __restrict__ Yout,
                        __half2* __restrict__ XYout,
                        const float* __restrict__ al, const float* __restrict__ be,
                        const float* __restrict__ ga, const float* __restrict__ de,
                        int N) {
    int w = (blockIdx.x * blockDim.x + threadIdx.x) >> 5;
    int lane = threadIdx.x & 31;
    if (w >= N) return;
    int s0 = g_rowptr[w];
    int s1 = g_rowptr[w + 1];
    float ax0 = 0.f, ax1 = 0.f, ax2 = 0.f;
    float ay0 = 0.f, ay1 = 0.f, ay2 = 0.f;
    for (int e = s0; e < s1; ++e) {
        int s = __ldg(&g_srcs[e]);
        const __half2* p = XYin + (size_t)s * H;
        float2 v0 = __half22float2(__ldg(p + lane));
        float2 v1 = __half22float2(__ldg(p + lane + 32));
        float2 v2 = __half22float2(__ldg(p + lane + 64));
        ax0 += v0.x; ay0 += v0.y;
        ax1 += v1.x; ay1 += v1.y;
        ax2 += v2.x; ay2 += v2.y;
    }
    float dinv = g_deginv[w];
    float aggx[3] = {ax0 * dinv, ax1 * dinv, ax2 * dinv};
    float aggy[3] = {ay0 * dinv, ay1 * dinv, ay2 * dinv};
    size_t base = (size_t)w * H;
#pragma unroll
    for (int j = 0; j < 3; ++j) {
        int c = lane + 32 * j;
        float Xv = Xin[base + c];
        float Yv = Yin[base + c];
        float Xn = Xv + DTC * Xv * (al[c] - be[c] * aggy[j]);
        float Yn = Yv + DTC * Yv * (-ga[c] + de[c] * aggx[j]);
        Xout[base + c] = Xn;
        Yout[base + c] = Yn;
        XYout[base + c] = __floats2half2_rn(Xn, Yn);
    }
}

// ---------------- readout: out = [X|Y] @ Wr + br ----------------
__global__ void k_readout(const float* __restrict__ Xf, const float* __restrict__ Yf,
                          const float* __restrict__ Wr, const float* __restrict__ br,
                          float* __restrict__ out, int N) {
    __shared__ float xs[128][33];
    __shared__ float ws[32][COUT];
    int tid = threadIdx.x;
    int tx = tid & 7;
    int ty = tid >> 3;
    int row0 = blockIdx.x * 128;
    float acc[8][5];
#pragma unroll
    for (int i = 0; i < 8; ++i)
#pragma unroll
        for (int j = 0; j < 5; ++j) acc[i][j] = 0.f;

    for (int kt = 0; kt < 2 * H; kt += 32) {
        const float* srcm = (kt < H) ? Xf : Yf;
        int kof = (kt < H) ? kt : (kt - H);
#pragma unroll
        for (int j = 0; j < 8; ++j) {
            int f4 = tid + j * 128;
            int r = f4 >> 3;
            int kq = f4 & 7;
            float4 v = make_float4(0.f, 0.f, 0.f, 0.f);
            int gr = row0 + r;
            if (gr < N) v = *(const float4*)(srcm + (size_t)gr * H + kof + kq * 4);
            xs[r][kq * 4 + 0] = v.x; xs[r][kq * 4 + 1] = v.y;
            xs[r][kq * 4 + 2] = v.z; xs[r][kq * 4 + 3] = v.w;
        }
#pragma unroll
        for (int j = 0; j < 10; ++j) {
            int idx = tid + j * 128;
            if (idx < 32 * COUT) {
                int k = idx / COUT;
                int c = idx - k * COUT;
                ws[k][c] = Wr[(size_t)(kt + k) * COUT + c];
            }
        }
        __syncthreads();
#pragma unroll
        for (int k = 0; k < 32; ++k) {
            float xv[8];
#pragma unroll
            for (int i = 0; i < 8; ++i) xv[i] = xs[ty * 8 + i][k];
            float wv[5];
#pragma unroll
            for (int j = 0; j < 5; ++j) wv[j] = ws[k][tx * 5 + j];
#pragma unroll
            for (int i = 0; i < 8; ++i)
#pragma unroll
                for (int j = 0; j < 5; ++j) acc[i][j] += xv[i] * wv[j];
        }
        __syncthreads();
    }
#pragma unroll
    for (int i = 0; i < 8; ++i) {
        int gr = row0 + ty * 8 + i;
        if (gr < N) {
#pragma unroll
            for (int j = 0; j < 5; ++j)
                out[(size_t)gr * COUT + tx * 5 + j] = acc[i][j] + br[tx * 5 + j];
        }
    }
}

// ---------------- launch ----------------
extern "C" void kernel_launch(void* const* d_in, const int* in_sizes, int n_in,
                              void* d_out, int out_size) {
    const float* x  = (const float*)d_in[0];
    const int*   ei = (const int*)d_in[1];
    const float* Wx = (const float*)d_in[2];
    const float* bx = (const float*)d_in[3];
    const float* Wy = (const float*)d_in[4];
    const float* by = (const float*)d_in[5];
    const float* al = (const float*)d_in[6];
    const float* be = (const float*)d_in[7];
    const float* ga = (const float*)d_in[8];
    const float* de = (const float*)d_in[9];
    const float* Wr = (const float*)d_in[10];
    const float* br = (const float*)d_in[11];
    float* out = (float*)d_out;

    int N = in_sizes[0] / CIN;
    int E = in_sizes[1] / 2;
    if (N > NMAX) N = NMAX;
    if (E > EMAX) E = EMAX;
    const int* srcp = ei;
    const int* dstp = ei + E;

    void* degp;
    cudaGetSymbolAddress(&degp, g_deg);
    cudaMemsetAsync(degp, 0, (size_t)N * sizeof(int));

    k_deg<<<(E + 255) / 256, 256>>>(dstp, E);
    k_scan<<<1, 1024>>>(N);
    k_scatter<<<(E + 255) / 256, 256>>>(srcp, dstp, E);

    dim3 gl((N + 127) / 128, 3);
    k_lift<<<gl, 128>>>(x, Wx, bx, Wy, by, N);

    float* Xb[2]; float* Yb[2]; __half2* XYb[2];
    cudaGetSymbolAddress((void**)&Xb[0], g_X0);
    cudaGetSymbolAddress((void**)&Yb[0], g_Y0);
    cudaGetSymbolAddress((void**)&Xb[1], g_X1);
    cudaGetSymbolAddress((void**)&Yb[1], g_Y1);
    cudaGetSymbolAddress((void**)&XYb[0], g_XY0);
    cudaGetSymbolAddress((void**)&XYb[1], g_XY1);

    int total = N * H;
    k_pack<<<(total + 255) / 256, 256>>>(Xb[0], Yb[0], XYb[0], total);

    int layerBlocks = (N * 32 + 255) / 256;
    for (int l = 0; l < NLAYER; ++l) {
        k_layer<<<layerBlocks, 256>>>(Xb[l & 1], Yb[l & 1], XYb[l & 1],
                                      Xb[(l + 1) & 1], Yb[(l + 1) & 1], XYb[(l + 1) & 1],
                                      al + l * H, be + l * H, ga + l * H, de + l * H, N);
    }
    k_readout<<<(N + 127) / 128, 128>>>(Xb[NLAYER & 1], Yb[NLAYER & 1], Wr, br, out, N);
}

// round 3
// speedup vs baseline: 1.1082x; 1.0508x over previous
#include <cuda_runtime.h>
#include <cuda_fp16.h>

#define NMAX   50000
#define EMAX   800000
#define H      96
#define CIN    128
#define COUT   40
#define NLAYER 5
#define DTC    0.05f

// ---------------- device scratch (static, no allocs) ----------------
__device__ int   g_deg[NMAX];
__device__ int   g_rowptr[NMAX + 1];
__device__ int   g_cursor[NMAX];
__device__ float g_deginv[NMAX];
__device__ int   g_srcs[EMAX];
__device__ float g_X0[(size_t)NMAX * H];
__device__ float g_Y0[(size_t)NMAX * H];
__device__ float g_X1[(size_t)NMAX * H];
__device__ float g_Y1[(size_t)NMAX * H];
__device__ __half2 g_XY0[(size_t)NMAX * H];   // interleaved (X,Y), fp16, gather-only
__device__ __half2 g_XY1[(size_t)NMAX * H];

// ---------------- f32x2 packed-FMA helpers ----------------
__device__ __forceinline__ unsigned long long pack2(float v) {
    unsigned long long r; unsigned int u = __float_as_uint(v);
    asm("mov.b64 %0, {%1, %1};" : "=l"(r) : "r"(u));
    return r;
}
__device__ __forceinline__ void unpack2(unsigned long long v, float& a, float& b) {
    unsigned int x, y;
    asm("mov.b64 {%0, %1}, %2;" : "=r"(x), "=r"(y) : "l"(v));
    a = __uint_as_float(x); b = __uint_as_float(y);
}
__device__ __forceinline__ void ffma2(unsigned long long& d,
                                      unsigned long long a, unsigned long long b) {
    asm("fma.rn.f32x2 %0, %1, %2, %0;" : "+l"(d) : "l"(a), "l"(b));
}

// ---------------- CSR build ----------------
__global__ void k_deg(const int* __restrict__ dst, int E) {
    int e = blockIdx.x * blockDim.x + threadIdx.x;
    if (e < E) atomicAdd(&g_deg[dst[e]], 1);
}

__global__ void k_scan(int N) {
    __shared__ int sm[1024];
    int tid = threadIdx.x;
    int per = (N + 1023) >> 10;
    int b = tid * per;
    int e = b + per; if (e > N) e = N; if (b > N) b = N;
    int sum = 0;
    for (int i = b; i < e; ++i) sum += g_deg[i];
    sm[tid] = sum;
    __syncthreads();
    for (int off = 1; off < 1024; off <<= 1) {
        int v = 0;
        if (tid >= off) v = sm[tid - off];
        __syncthreads();
        sm[tid] += v;
        __syncthreads();
    }
    int run = sm[tid] - sum;  // exclusive prefix
    for (int i = b; i < e; ++i) {
        int dg = g_deg[i];
        g_rowptr[i] = run;
        g_cursor[i] = run;
        g_deginv[i] = 1.0f / (float)(dg > 1 ? dg : 1);
        run += dg;
    }
    if (tid == 0) g_rowptr[N] = sm[1023];
}

__global__ void k_scatter(const int* __restrict__ src, const int* __restrict__ dst, int E) {
    int e = blockIdx.x * blockDim.x + threadIdx.x;
    if (e < E) {
        int p = atomicAdd(&g_cursor[dst[e]], 1);
        g_srcs[p] = src[e];
    }
}

// ---------------- lift: X = tanh(x@Wx+bx), Y = tanh(x@Wy+by) ----------------
// C[N x 192] = x[N x 128] @ [Wx | Wy]. 256 threads/block, block tile 128x64,
// thread tile 8 rows x 4 cols (2 packed f32x2 accumulator pairs per row).
__global__ __launch_bounds__(256) void k_lift(
        const float* __restrict__ x,
        const float* __restrict__ Wx, const float* __restrict__ bx,
        const float* __restrict__ Wy, const float* __restrict__ by,
        int N) {
    __shared__ __align__(16) float xs[128][33];
    __shared__ __align__(16) float ws[32][64];
    int tid = threadIdx.x;
    int tx = tid & 15;       // col group (16), 4 cols each
    int ty = tid >> 4;       // row group (16), 8 rows each
    int cb = blockIdx.y;     // 0..2
    int row0 = blockIdx.x * 128;

    unsigned long long acc[8][2];
#pragma unroll
    for (int i = 0; i < 8; ++i) { acc[i][0] = 0ull; acc[i][1] = 0ull; }

    for (int kt = 0; kt < CIN; kt += 32) {
        // xs: 128x32 floats = 1024 float4 -> 4 per thread
#pragma unroll
        for (int j = 0; j < 4; ++j) {
            int f4 = tid + j * 256;
            int r = f4 >> 3;
            int kq = f4 & 7;
            float4 v = make_float4(0.f, 0.f, 0.f, 0.f);
            int gr = row0 + r;
            if (gr < N) v = *(const float4*)(x + (size_t)gr * CIN + kt + kq * 4);
            xs[r][kq * 4 + 0] = v.x; xs[r][kq * 4 + 1] = v.y;
            xs[r][kq * 4 + 2] = v.z; xs[r][kq * 4 + 3] = v.w;
        }
        // ws: 32x64 of virtual [Wx|Wy] -> 8 scalars per thread
#pragma unroll
        for (int j = 0; j < 8; ++j) {
            int idx = tid + j * 256;   // 0..2047
            int k = idx >> 6;
            int c = idx & 63;
            int gc = cb * 64 + c;
            int gk = kt + k;
            float w = (gc < H) ? Wx[gk * H + gc] : Wy[gk * H + (gc - H)];
            ws[k][c] = w;
        }
        __syncthreads();
#pragma unroll
        for (int k = 0; k < 32; ++k) {
            const unsigned long long* wp =
                reinterpret_cast<const unsigned long long*>(&ws[k][tx * 4]);
            unsigned long long b0 = wp[0], b1 = wp[1];
#pragma unroll
            for (int i = 0; i < 8; ++i) {
                unsigned long long a2 = pack2(xs[ty * 8 + i][k]);
                ffma2(acc[i][0], a2, b0);
                ffma2(acc[i][1], a2, b1);
            }
        }
        __syncthreads();
    }
    // epilogue: each thread's 4-col chunk is entirely in X (cols<96) or Y.
    int c0 = cb * 64 + tx * 4;
    bool isX = (c0 < H);
    int cc0 = isX ? c0 : (c0 - H);
    float bb[4];
#pragma unroll
    for (int j = 0; j < 4; ++j) bb[j] = isX ? bx[cc0 + j] : by[cc0 + j];
    float* outp = isX ? g_X0 : g_Y0;
#pragma unroll
    for (int i = 0; i < 8; ++i) {
        int gr = row0 + ty * 8 + i;
        if (gr < N) {
            float v0, v1, v2, v3;
            unpack2(acc[i][0], v0, v1);
            unpack2(acc[i][1], v2, v3);
            float4 o;
            o.x = tanhf(v0 + bb[0]);
            o.y = tanhf(v1 + bb[1]);
            o.z = tanhf(v2 + bb[2]);
            o.w = tanhf(v3 + bb[3]);
            *(float4*)(outp + (size_t)gr * H + cc0) = o;
        }
    }
}

// ---------------- pack fp32 X,Y -> interleaved half2 XY ----------------
__global__ void k_pack(const float* __restrict__ X, const float* __restrict__ Y,
                       __half2* __restrict__ XY, int total) {
    int i = blockIdx.x * blockDim.x + threadIdx.x;
    if (i < total) XY[i] = __floats2half2_rn(X[i], Y[i]);
}

// ---------------- one LVConv layer ----------------
// warp per dst node; 4x-unrolled prefetched fp16 gather (12 LDGs in flight),
// fp32 pointwise Euler update, dual write (fp32 state + half2 gather copy).
__global__ __launch_bounds__(256) void k_layer(
        const float* __restrict__ Xin, const float* __restrict__ Yin,
        const __half2* __restrict__ XYin,
        float* __restrict__ Xout, float* __restrict__ Yout,
        __half2* __restrict__ XYout,
        const float* __restrict__ al, const float* __restrict__ be,
        const float* __restrict__ ga, const float* __restrict__ de,
        int N) {
    int w = (blockIdx.x * blockDim.x + threadIdx.x) >> 5;
    int lane = threadIdx.x & 31;
    if (w >= N) return;
    int s0 = __ldg(&g_rowptr[w]);
    int s1 = __ldg(&g_rowptr[w + 1]);
    float ax0 = 0.f, ax1 = 0.f, ax2 = 0.f;
    float ay0 = 0.f, ay1 = 0.f, ay2 = 0.f;

    int e = s0;
    for (; e + 4 <= s1; e += 4) {
        int sA = __ldg(&g_srcs[e + 0]);
        int sB = __ldg(&g_srcs[e + 1]);
        int sC = __ldg(&g_srcs[e + 2]);
        int sD = __ldg(&g_srcs[e + 3]);
        const __half2* pA = XYin + (size_t)sA * H + lane;
        const __half2* pB = XYin + (size_t)sB * H + lane;
        const __half2* pC = XYin + (size_t)sC * H + lane;
        const __half2* pD = XYin + (size_t)sD * H + lane;
        // issue all 12 loads before consuming any
        __half2 a0 = __ldg(pA);      __half2 a1 = __ldg(pA + 32); __half2 a2 = __ldg(pA + 64);
        __half2 b0 = __ldg(pB);      __half2 b1 = __ldg(pB + 32); __half2 b2 = __ldg(pB + 64);
        __half2 c0 = __ldg(pC);      __half2 c1 = __ldg(pC + 32); __half2 c2 = __ldg(pC + 64);
        __half2 d0 = __ldg(pD);      __half2 d1 = __ldg(pD + 32); __half2 d2 = __ldg(pD + 64);
        // pairwise half2 adds (exact-ish small sums), then float accumulate
        __half2 s0h = __hadd2(a0, b0), t0h = __hadd2(c0, d0);
        __half2 s1h = __hadd2(a1, b1), t1h = __hadd2(c1, d1);
        __half2 s2h = __hadd2(a2, b2), t2h = __hadd2(c2, d2);
        float2 f0 = __half22float2(s0h), g0 = __half22float2(t0h);
        float2 f1 = __half22float2(s1h), g1 = __half22float2(t1h);
        float2 f2 = __half22float2(s2h), g2 = __half22float2(t2h);
        ax0 += f0.x + g0.x; ay0 += f0.y + g0.y;
        ax1 += f1.x + g1.x; ay1 += f1.y + g1.y;
        ax2 += f2.x + g2.x; ay2 += f2.y + g2.y;
    }
    for (; e < s1; ++e) {
        int s = __ldg(&g_srcs[e]);
        const __half2* p = XYin + (size_t)s * H + lane;
        float2 v0 = __half22float2(__ldg(p));
        float2 v1 = __half22float2(__ldg(p + 32));
        float2 v2 = __half22float2(__ldg(p + 64));
        ax0 += v0.x; ay0 += v0.y;
        ax1 += v1.x; ay1 += v1.y;
        ax2 += v2.x; ay2 += v2.y;
    }
    float dinv = __ldg(&g_deginv[w]);
    float aggx[3] = {ax0 * dinv, ax1 * dinv, ax2 * dinv};
    float aggy[3] = {ay0 * dinv, ay1 * dinv, ay2 * dinv};
    size_t base = (size_t)w * H;
#pragma unroll
    for (int j = 0; j < 3; ++j) {
        int c = lane + 32 * j;
        float Xv = Xin[base + c];
        float Yv = Yin[base + c];
        float Xn = Xv + DTC * Xv * (__ldg(al + c) - __ldg(be + c) * aggy[j]);
        float Yn = Yv + DTC * Yv * (-__ldg(ga + c) + __ldg(de + c) * aggx[j]);
        Xout[base + c] = Xn;
        Yout[base + c] = Yn;
        XYout[base + c] = __floats2half2_rn(Xn, Yn);
    }
}

// ---------------- readout: out = [X|Y] @ Wr + br ----------------
__global__ void k_readout(const float* __restrict__ Xf, const float* __restrict__ Yf,
                          const float* __restrict__ Wr, const float* __restrict__ br,
                          float* __restrict__ out, int N) {
    __shared__ float xs[128][33];
    __shared__ float ws[32][COUT];
    int tid = threadIdx.x;
    int tx = tid & 7;
    int ty = tid >> 3;
    int row0 = blockIdx.x * 128;
    float acc[8][5];
#pragma unroll
    for (int i = 0; i < 8; ++i)
#pragma unroll
        for (int j = 0; j < 5; ++j) acc[i][j] = 0.f;

    for (int kt = 0; kt < 2 * H; kt += 32) {
        const float* srcm = (kt < H) ? Xf : Yf;
        int kof = (kt < H) ? kt : (kt - H);
#pragma unroll
        for (int j = 0; j < 8; ++j) {
            int f4 = tid + j * 128;
            int r = f4 >> 3;
            int kq = f4 & 7;
            float4 v = make_float4(0.f, 0.f, 0.f, 0.f);
            int gr = row0 + r;
            if (gr < N) v = *(const float4*)(srcm + (size_t)gr * H + kof + kq * 4);
            xs[r][kq * 4 + 0] = v.x; xs[r][kq * 4 + 1] = v.y;
            xs[r][kq * 4 + 2] = v.z; xs[r][kq * 4 + 3] = v.w;
        }
#pragma unroll
        for (int j = 0; j < 10; ++j) {
            int idx = tid + j * 128;
            if (idx < 32 * COUT) {
                int k = idx / COUT;
                int c = idx - k * COUT;
                ws[k][c] = Wr[(size_t)(kt + k) * COUT + c];
            }
        }
        __syncthreads();
#pragma unroll
        for (int k = 0; k < 32; ++k) {
            float xv[8];
#pragma unroll
            for (int i = 0; i < 8; ++i) xv[i] = xs[ty * 8 + i][k];
            float wv[5];
#pragma unroll
            for (int j = 0; j < 5; ++j) wv[j] = ws[k][tx * 5 + j];
#pragma unroll
            for (int i = 0; i < 8; ++i)
#pragma unroll
                for (int j = 0; j < 5; ++j) acc[i][j] += xv[i] * wv[j];
        }
        __syncthreads();
    }
#pragma unroll
    for (int i = 0; i < 8; ++i) {
        int gr = row0 + ty * 8 + i;
        if (gr < N) {
#pragma unroll
            for (int j = 0; j < 5; ++j)
                out[(size_t)gr * COUT + tx * 5 + j] = acc[i][j] + br[tx * 5 + j];
        }
    }
}

// ---------------- launch ----------------
extern "C" void kernel_launch(void* const* d_in, const int* in_sizes, int n_in,
                              void* d_out, int out_size) {
    const float* x  = (const float*)d_in[0];
    const int*   ei = (const int*)d_in[1];
    const float* Wx = (const float*)d_in[2];
    const float* bx = (const float*)d_in[3];
    const float* Wy = (const float*)d_in[4];
    const float* by = (const float*)d_in[5];
    const float* al = (const float*)d_in[6];
    const float* be = (const float*)d_in[7];
    const float* ga = (const float*)d_in[8];
    const float* de = (const float*)d_in[9];
    const float* Wr = (const float*)d_in[10];
    const float* br = (const float*)d_in[11];
    float* out = (float*)d_out;

    int N = in_sizes[0] / CIN;
    int E = in_sizes[1] / 2;
    if (N > NMAX) N = NMAX;
    if (E > EMAX) E = EMAX;
    const int* srcp = ei;
    const int* dstp = ei + E;

    void* degp;
    cudaGetSymbolAddress(&degp, g_deg);
    cudaMemsetAsync(degp, 0, (size_t)N * sizeof(int));

    k_deg<<<(E + 255) / 256, 256>>>(dstp, E);
    k_scan<<<1, 1024>>>(N);
    k_scatter<<<(E + 255) / 256, 256>>>(srcp, dstp, E);

    dim3 gl((N + 127) / 128, 3);
    k_lift<<<gl, 256>>>(x, Wx, bx, Wy, by, N);

    float* Xb[2]; float* Yb[2]; __half2* XYb[2];
    cudaGetSymbolAddress((void**)&Xb[0], g_X0);
    cudaGetSymbolAddress((void**)&Yb[0], g_Y0);
    cudaGetSymbolAddress((void**)&Xb[1], g_X1);
    cudaGetSymbolAddress((void**)&Yb[1], g_Y1);
    cudaGetSymbolAddress((void**)&XYb[0], g_XY0);
    cudaGetSymbolAddress((void**)&XYb[1], g_XY1);

    int total = N * H;
    k_pack<<<(total + 255) / 256, 256>>>(Xb[0], Yb[0], XYb[0], total);

    int layerBlocks = (N * 32 + 255) / 256;
    for (int l = 0; l < NLAYER; ++l) {
        k_layer<<<layerBlocks, 256>>>(Xb[l & 1], Yb[l & 1], XYb[l & 1],
                                      Xb[(l + 1) & 1], Yb[(l + 1) & 1], XYb[(l + 1) & 1],
                                      al + l * H, be + l * H, ga + l * H, de + l * H, N);
    }
    k_readout<<<(N + 127) / 128, 128>>>(Xb[NLAYER & 1], Yb[NLAYER & 1], Wr, br, out, N);
}

// round 4
// speedup vs baseline: 1.1847x; 1.0691x over previous
#include <cuda_runtime.h>
#include <cuda_fp16.h>

#define NMAX   50000
#define EMAX   800000
#define H      96
#define CIN    128
#define COUT   40
#define NLAYER 5
#define DTC    0.05f

// ---------------- device scratch (static, no allocs) ----------------
__device__ int   g_deg[NMAX];
__device__ int   g_rowptr[NMAX + 1];
__device__ int   g_cursor[NMAX];
__device__ float g_deginv[NMAX];
__device__ int   g_srcs[EMAX];
// state ping-pong: interleaved (X,Y) float2 per channel
__device__ float2  g_S0[(size_t)NMAX * H];
__device__ float2  g_S1[(size_t)NMAX * H];
// gather copies: interleaved (X,Y) half2 per channel (row = 96 half2 = 24 uint4)
__device__ __half2 g_XY0[(size_t)NMAX * H];
__device__ __half2 g_XY1[(size_t)NMAX * H];

// ---------------- f32x2 packed-FMA helpers ----------------
__device__ __forceinline__ unsigned long long pack2(float v) {
    unsigned long long r; unsigned int u = __float_as_uint(v);
    asm("mov.b64 %0, {%1, %1};" : "=l"(r) : "r"(u));
    return r;
}
__device__ __forceinline__ void unpack2(unsigned long long v, float& a, float& b) {
    unsigned int x, y;
    asm("mov.b64 {%0, %1}, %2;" : "=r"(x), "=r"(y) : "l"(v));
    a = __uint_as_float(x); b = __uint_as_float(y);
}
__device__ __forceinline__ void ffma2(unsigned long long& d,
                                      unsigned long long a, unsigned long long b) {
    asm("fma.rn.f32x2 %0, %1, %2, %0;" : "+l"(d) : "l"(a), "l"(b));
}

// ---------------- CSR build ----------------
__global__ void k_deg(const int* __restrict__ dst, int E) {
    int e = blockIdx.x * blockDim.x + threadIdx.x;
    if (e < E) atomicAdd(&g_deg[dst[e]], 1);
}

__global__ void k_scan(int N) {
    __shared__ int sm[1024];
    int tid = threadIdx.x;
    int per = (N + 1023) >> 10;
    int b = tid * per;
    int e = b + per; if (e > N) e = N; if (b > N) b = N;
    int sum = 0;
    for (int i = b; i < e; ++i) sum += g_deg[i];
    sm[tid] = sum;
    __syncthreads();
    for (int off = 1; off < 1024; off <<= 1) {
        int v = 0;
        if (tid >= off) v = sm[tid - off];
        __syncthreads();
        sm[tid] += v;
        __syncthreads();
    }
    int run = sm[tid] - sum;  // exclusive prefix
    for (int i = b; i < e; ++i) {
        int dg = g_deg[i];
        g_rowptr[i] = run;
        g_cursor[i] = run;
        g_deginv[i] = 1.0f / (float)(dg > 1 ? dg : 1);
        run += dg;
    }
    if (tid == 0) g_rowptr[N] = sm[1023];
}

__global__ void k_scatter(const int* __restrict__ src, const int* __restrict__ dst, int E) {
    int e = blockIdx.x * blockDim.x + threadIdx.x;
    if (e < E) {
        int p = atomicAdd(&g_cursor[dst[e]], 1);
        g_srcs[p] = src[e];
    }
}

// ---------------- lift ----------------
// Pair-GEMM: S[N][96] (float2) = tanh(x @ [Wx,Wy] pairwise) via f32x2 where
// the packed lane pair IS (X_c, Y_c). Block tile 128 rows x 32 pairs,
// 256 threads, thread tile 8 rows x 2 pairs. Writes fp32 state AND half2 copy.
__global__ __launch_bounds__(256) void k_lift(
        const float* __restrict__ x,
        const float* __restrict__ Wx, const float* __restrict__ bx,
        const float* __restrict__ Wy, const float* __restrict__ by,
        int N) {
    __shared__ __align__(16) float  xs[128][33];
    __shared__ __align__(16) float2 ws[32][32];   // (Wx,Wy) pairs
    int tid = threadIdx.x;
    int tx = tid & 15;       // pair group (16), 2 pairs each
    int ty = tid >> 4;       // row group (16), 8 rows each
    int cb = blockIdx.y;     // 0..2 (32 pairs each)
    int row0 = blockIdx.x * 128;

    unsigned long long acc[8][2];
#pragma unroll
    for (int i = 0; i < 8; ++i) { acc[i][0] = 0ull; acc[i][1] = 0ull; }

    for (int kt = 0; kt < CIN; kt += 32) {
        // xs: 128x32 floats -> 4 float4 per thread
#pragma unroll
        for (int j = 0; j < 4; ++j) {
            int f4 = tid + j * 256;
            int r = f4 >> 3;
            int kq = f4 & 7;
            float4 v = make_float4(0.f, 0.f, 0.f, 0.f);
            int gr = row0 + r;
            if (gr < N) v = *(const float4*)(x + (size_t)gr * CIN + kt + kq * 4);
            xs[r][kq * 4 + 0] = v.x; xs[r][kq * 4 + 1] = v.y;
            xs[r][kq * 4 + 2] = v.z; xs[r][kq * 4 + 3] = v.w;
        }
        // ws: 32x32 (Wx,Wy) pairs -> 4 pairs per thread
#pragma unroll
        for (int j = 0; j < 4; ++j) {
            int idx = tid + j * 256;   // 0..1023
            int k = idx >> 5;
            int p = idx & 31;
            int gp = cb * 32 + p;
            int gk = kt + k;
            ws[k][p] = make_float2(Wx[gk * H + gp], Wy[gk * H + gp]);
        }
        __syncthreads();
#pragma unroll
        for (int k = 0; k < 32; ++k) {
            const unsigned long long* wp =
                reinterpret_cast<const unsigned long long*>(&ws[k][tx * 2]);
            unsigned long long b0 = wp[0], b1 = wp[1];
#pragma unroll
            for (int i = 0; i < 8; ++i) {
                unsigned long long a2 = pack2(xs[ty * 8 + i][k]);
                ffma2(acc[i][0], a2, b0);
                ffma2(acc[i][1], a2, b1);
            }
        }
        __syncthreads();
    }
    // epilogue: tanh both species, write float2 state + half2 gather copy
    int c0 = cb * 32 + tx * 2;
    float bx0 = bx[c0], by0 = by[c0], bx1 = bx[c0 + 1], by1 = by[c0 + 1];
#pragma unroll
    for (int i = 0; i < 8; ++i) {
        int gr = row0 + ty * 8 + i;
        if (gr < N) {
            float x0, y0, x1, y1;
            unpack2(acc[i][0], x0, y0);
            unpack2(acc[i][1], x1, y1);
            float2 p0 = make_float2(tanhf(x0 + bx0), tanhf(y0 + by0));
            float2 p1 = make_float2(tanhf(x1 + bx1), tanhf(y1 + by1));
            size_t base = (size_t)gr * H + c0;
            float4 st; st.x = p0.x; st.y = p0.y; st.z = p1.x; st.w = p1.y;
            *(float4*)(&g_S0[base]) = st;
            __half2 h0 = __floats2half2_rn(p0.x, p0.y);
            __half2 h1 = __floats2half2_rn(p1.x, p1.y);
            g_XY0[base] = h0;
            g_XY0[base + 1] = h1;
        }
    }
}

// ---------------- one LVConv layer ----------------
// warp per dst node. Gather: lanes 0..23 each load the full row slice as ONE
// LDG.128 (uint4 = 4 half2 = 4 channel-pairs), accumulate with HADD2.
// Epilogue: fp32 Euler update from interleaved float2 state.
__global__ __launch_bounds__(256) void k_layer(
        const float2* __restrict__ Sin,
        const uint4* __restrict__ XYin,     // rows of 24 uint4
        float2* __restrict__ Sout,
        __half2* __restrict__ XYout,
        const float* __restrict__ al, const float* __restrict__ be,
        const float* __restrict__ ga, const float* __restrict__ de,
        int N) {
    int w = (blockIdx.x * blockDim.x + threadIdx.x) >> 5;
    int lane = threadIdx.x & 31;
    if (w >= N) return;
    bool act = lane < 24;
    int s0 = __ldg(&g_rowptr[w]);
    int s1 = __ldg(&g_rowptr[w + 1]);

    __half2 acc0 = __floats2half2_rn(0.f, 0.f);
    __half2 acc1 = acc0, acc2 = acc0, acc3 = acc0;

    int e = s0;
    for (; e + 4 <= s1; e += 4) {
        int sA = __ldg(&g_srcs[e + 0]);
        int sB = __ldg(&g_srcs[e + 1]);
        int sC = __ldg(&g_srcs[e + 2]);
        int sD = __ldg(&g_srcs[e + 3]);
        if (act) {
            uint4 vA = __ldg(XYin + (size_t)sA * 24 + lane);
            uint4 vB = __ldg(XYin + (size_t)sB * 24 + lane);
            uint4 vC = __ldg(XYin + (size_t)sC * 24 + lane);
            uint4 vD = __ldg(XYin + (size_t)sD * 24 + lane);
            acc0 = __hadd2(acc0, __hadd2(__hadd2(*(__half2*)&vA.x, *(__half2*)&vB.x),
                                         __hadd2(*(__half2*)&vC.x, *(__half2*)&vD.x)));
            acc1 = __hadd2(acc1, __hadd2(__hadd2(*(__half2*)&vA.y, *(__half2*)&vB.y),
                                         __hadd2(*(__half2*)&vC.y, *(__half2*)&vD.y)));
            acc2 = __hadd2(acc2, __hadd2(__hadd2(*(__half2*)&vA.z, *(__half2*)&vB.z),
                                         __hadd2(*(__half2*)&vC.z, *(__half2*)&vD.z)));
            acc3 = __hadd2(acc3, __hadd2(__hadd2(*(__half2*)&vA.w, *(__half2*)&vB.w),
                                         __hadd2(*(__half2*)&vC.w, *(__half2*)&vD.w)));
        }
    }
    for (; e < s1; ++e) {
        int s = __ldg(&g_srcs[e]);
        if (act) {
            uint4 v = __ldg(XYin + (size_t)s * 24 + lane);
            acc0 = __hadd2(acc0, *(__half2*)&v.x);
            acc1 = __hadd2(acc1, *(__half2*)&v.y);
            acc2 = __hadd2(acc2, *(__half2*)&v.z);
            acc3 = __hadd2(acc3, *(__half2*)&v.w);
        }
    }
    if (!act) return;

    float dinv = __ldg(&g_deginv[w]);
    float2 a0 = __half22float2(acc0);
    float2 a1 = __half22float2(acc1);
    float2 a2 = __half22float2(acc2);
    float2 a3 = __half22float2(acc3);
    // agg per channel: .x = aggX, .y = aggY
    float aggX[4] = {a0.x * dinv, a1.x * dinv, a2.x * dinv, a3.x * dinv};
    float aggY[4] = {a0.y * dinv, a1.y * dinv, a2.y * dinv, a3.y * dinv};

    int c0 = lane * 4;
    size_t base = (size_t)w * H + c0;
    const float4* Sp = (const float4*)(Sin + base);
    float4 s01 = __ldg(Sp);       // ch c0:   (X0,Y0,X1,Y1)
    float4 s23 = __ldg(Sp + 1);   // ch c0+2: (X2,Y2,X3,Y3)
    float4 alv = *(const float4*)(al + c0);
    float4 bev = *(const float4*)(be + c0);
    float4 gav = *(const float4*)(ga + c0);
    float4 dev = *(const float4*)(de + c0);

    float Xn0 = s01.x + DTC * s01.x * (alv.x - bev.x * aggY[0]);
    float Yn0 = s01.y + DTC * s01.y * (-gav.x + dev.x * aggX[0]);
    float Xn1 = s01.z + DTC * s01.z * (alv.y - bev.y * aggY[1]);
    float Yn1 = s01.w + DTC * s01.w * (-gav.y + dev.y * aggX[1]);
    float Xn2 = s23.x + DTC * s23.x * (alv.z - bev.z * aggY[2]);
    float Yn2 = s23.y + DTC * s23.y * (-gav.z + dev.z * aggX[2]);
    float Xn3 = s23.z + DTC * s23.z * (alv.w - bev.w * aggY[3]);
    float Yn3 = s23.w + DTC * s23.w * (-gav.w + dev.w * aggX[3]);

    float4* Op = (float4*)(Sout + base);
    float4 o0; o0.x = Xn0; o0.y = Yn0; o0.z = Xn1; o0.w = Yn1;
    float4 o1; o1.x = Xn2; o1.y = Yn2; o1.z = Xn3; o1.w = Yn3;
    Op[0] = o0;
    Op[1] = o1;

    __half2 h0 = __floats2half2_rn(Xn0, Yn0);
    __half2 h1 = __floats2half2_rn(Xn1, Yn1);
    __half2 h2 = __floats2half2_rn(Xn2, Yn2);
    __half2 h3 = __floats2half2_rn(Xn3, Yn3);
    uint4 hv;
    hv.x = *(unsigned int*)&h0; hv.y = *(unsigned int*)&h1;
    hv.z = *(unsigned int*)&h2; hv.w = *(unsigned int*)&h3;
    *(uint4*)(XYout + base) = hv;
}

// ---------------- readout: out = [X|Y] @ Wr + br, from interleaved state ----
__global__ __launch_bounds__(128) void k_readout(
        const float2* __restrict__ S,
        const float* __restrict__ Wr, const float* __restrict__ br,
        float* __restrict__ out, int N) {
    __shared__ float2 xs2[128][33];
    __shared__ float  wsX[32][COUT];
    __shared__ float  wsY[32][COUT];
    int tid = threadIdx.x;
    int tx = tid & 7;
    int ty = tid >> 3;
    int row0 = blockIdx.x * 128;
    float acc[8][5];
#pragma unroll
    for (int i = 0; i < 8; ++i)
#pragma unroll
        for (int j = 0; j < 5; ++j) acc[i][j] = 0.f;

    for (int kt = 0; kt < H; kt += 32) {
        // load 128 rows x 32 channels of float2 = 2048 float4 -> 16/thread
#pragma unroll
        for (int j = 0; j < 16; ++j) {
            int f4 = tid + j * 128;
            int r = f4 >> 4;
            int q = f4 & 15;           // 16 float4 per 32-channel chunk
            float4 v = make_float4(0.f, 0.f, 0.f, 0.f);
            int gr = row0 + r;
            if (gr < N) v = *(const float4*)(S + (size_t)gr * H + kt + q * 2);
            xs2[r][q * 2 + 0] = make_float2(v.x, v.y);
            xs2[r][q * 2 + 1] = make_float2(v.z, v.w);
        }
        // W tiles: rows kt+k (X part) and H+kt+k (Y part)
#pragma unroll
        for (int j = 0; j < 10; ++j) {
            int idx = tid + j * 128;
            if (idx < 32 * COUT) {
                int k = idx / COUT;
                int c = idx - k * COUT;
                wsX[k][c] = Wr[(size_t)(kt + k) * COUT + c];
                wsY[k][c] = Wr[(size_t)(H + kt + k) * COUT + c];
            }
        }
        __syncthreads();
#pragma unroll
        for (int k = 0; k < 32; ++k) {
            float2 xv[8];
#pragma unroll
            for (int i = 0; i < 8; ++i) xv[i] = xs2[ty * 8 + i][k];
            float wx[5], wy[5];
#pragma unroll
            for (int j = 0; j < 5; ++j) { wx[j] = wsX[k][tx * 5 + j]; wy[j] = wsY[k][tx * 5 + j]; }
#pragma unroll
            for (int i = 0; i < 8; ++i)
#pragma unroll
                for (int j = 0; j < 5; ++j)
                    acc[i][j] += xv[i].x * wx[j] + xv[i].y * wy[j];
        }
        __syncthreads();
    }
#pragma unroll
    for (int i = 0; i < 8; ++i) {
        int gr = row0 + ty * 8 + i;
        if (gr < N) {
#pragma unroll
            for (int j = 0; j < 5; ++j)
                out[(size_t)gr * COUT + tx * 5 + j] = acc[i][j] + br[tx * 5 + j];
        }
    }
}

// ---------------- launch ----------------
extern "C" void kernel_launch(void* const* d_in, const int* in_sizes, int n_in,
                              void* d_out, int out_size) {
    const float* x  = (const float*)d_in[0];
    const int*   ei = (const int*)d_in[1];
    const float* Wx = (const float*)d_in[2];
    const float* bx = (const float*)d_in[3];
    const float* Wy = (const float*)d_in[4];
    const float* by = (const float*)d_in[5];
    const float* al = (const float*)d_in[6];
    const float* be = (const float*)d_in[7];
    const float* ga = (const float*)d_in[8];
    const float* de = (const float*)d_in[9];
    const float* Wr = (const float*)d_in[10];
    const float* br = (const float*)d_in[11];
    float* out = (float*)d_out;

    int N = in_sizes[0] / CIN;
    int E = in_sizes[1] / 2;
    if (N > NMAX) N = NMAX;
    if (E > EMAX) E = EMAX;
    const int* srcp = ei;
    const int* dstp = ei + E;

    void* degp;
    cudaGetSymbolAddress(&degp, g_deg);
    cudaMemsetAsync(degp, 0, (size_t)N * sizeof(int));

    k_deg<<<(E + 255) / 256, 256>>>(dstp, E);
    k_scan<<<1, 1024>>>(N);
    k_scatter<<<(E + 255) / 256, 256>>>(srcp, dstp, E);

    dim3 gl((N + 127) / 128, 3);
    k_lift<<<gl, 256>>>(x, Wx, bx, Wy, by, N);

    float2* Sb[2]; __half2* XYb[2];
    cudaGetSymbolAddress((void**)&Sb[0], g_S0);
    cudaGetSymbolAddress((void**)&Sb[1], g_S1);
    cudaGetSymbolAddress((void**)&XYb[0], g_XY0);
    cudaGetSymbolAddress((void**)&XYb[1], g_XY1);

    int layerBlocks = (N * 32 + 255) / 256;
    for (int l = 0; l < NLAYER; ++l) {
        k_layer<<<layerBlocks, 256>>>(Sb[l & 1], (const uint4*)XYb[l & 1],
                                      Sb[(l + 1) & 1], XYb[(l + 1) & 1],
                                      al + l * H, be + l * H, ga + l * H, de + l * H, N);
    }
    k_readout<<<(N + 127) / 128, 128>>>(Sb[NLAYER & 1], Wr, br, out, N);
}

// round 5
// speedup vs baseline: 1.3413x; 1.1322x over previous
#include <cuda_runtime.h>
#include <cuda_fp16.h>

#define NMAX   50000
#define EMAX   800000
#define H      96
#define CIN    128
#define COUT   40
#define NLAYER 5
#define DTC    0.05f

// ---------------- device scratch (static, no allocs) ----------------
__device__ int   g_deg[NMAX];
__device__ int   g_rowptr[NMAX + 1];
__device__ int   g_cursor[NMAX];
__device__ float g_deginv[NMAX];
__device__ int   g_srcs[EMAX];
// state ping-pong: interleaved (X,Y) half2 per channel (row = 96 half2 = 24 uint4)
__device__ __align__(16) __half2 g_XY0[(size_t)NMAX * H];
__device__ __align__(16) __half2 g_XY1[(size_t)NMAX * H];

// ---------------- f32x2 packed-FMA helpers ----------------
__device__ __forceinline__ unsigned long long pack2(float v) {
    unsigned long long r; unsigned int u = __float_as_uint(v);
    asm("mov.b64 %0, {%1, %1};" : "=l"(r) : "r"(u));
    return r;
}
__device__ __forceinline__ void unpack2(unsigned long long v, float& a, float& b) {
    unsigned int x, y;
    asm("mov.b64 {%0, %1}, %2;" : "=r"(x), "=r"(y) : "l"(v));
    a = __uint_as_float(x); b = __uint_as_float(y);
}
__device__ __forceinline__ void ffma2(unsigned long long& d,
                                      unsigned long long a, unsigned long long b) {
    asm("fma.rn.f32x2 %0, %1, %2, %0;" : "+l"(d) : "l"(a), "l"(b));
}

// ---------------- CSR build ----------------
__global__ void k_deg(const int* __restrict__ dst, int E) {
    int e = blockIdx.x * blockDim.x + threadIdx.x;
    if (e < E) atomicAdd(&g_deg[dst[e]], 1);
}

__global__ void k_scan(int N) {
    __shared__ int sm[1024];
    int tid = threadIdx.x;
    int per = (N + 1023) >> 10;
    int b = tid * per;
    int e = b + per; if (e > N) e = N; if (b > N) b = N;
    int sum = 0;
    for (int i = b; i < e; ++i) sum += g_deg[i];
    sm[tid] = sum;
    __syncthreads();
    for (int off = 1; off < 1024; off <<= 1) {
        int v = 0;
        if (tid >= off) v = sm[tid - off];
        __syncthreads();
        sm[tid] += v;
        __syncthreads();
    }
    int run = sm[tid] - sum;  // exclusive prefix
    for (int i = b; i < e; ++i) {
        int dg = g_deg[i];
        g_rowptr[i] = run;
        g_cursor[i] = run;
        g_deginv[i] = 1.0f / (float)(dg > 1 ? dg : 1);
        run += dg;
    }
    if (tid == 0) g_rowptr[N] = sm[1023];
}

__global__ void k_scatter(const int* __restrict__ src, const int* __restrict__ dst, int E) {
    int e = blockIdx.x * blockDim.x + threadIdx.x;
    if (e < E) {
        int p = atomicAdd(&g_cursor[dst[e]], 1);
        g_srcs[p] = src[e];
    }
}

// ---------------- lift ----------------
// Pair-GEMM: tanh(x @ [Wx,Wy]) via f32x2 where the packed lane pair IS
// (X_c, Y_c). Block tile 128 rows x 32 pairs, 256 threads, thread tile
// 8 rows x 2 pairs. Writes ONLY the half2-interleaved state.
__global__ __launch_bounds__(256) void k_lift(
        const float* __restrict__ x,
        const float* __restrict__ Wx, const float* __restrict__ bx,
        const float* __restrict__ Wy, const float* __restrict__ by,
        int N) {
    __shared__ __align__(16) float  xs[128][33];
    __shared__ __align__(16) float2 ws[32][32];   // (Wx,Wy) pairs
    int tid = threadIdx.x;
    int tx = tid & 15;       // pair group (16), 2 pairs each
    int ty = tid >> 4;       // row group (16), 8 rows each
    int cb = blockIdx.y;     // 0..2 (32 pairs each)
    int row0 = blockIdx.x * 128;

    unsigned long long acc[8][2];
#pragma unroll
    for (int i = 0; i < 8; ++i) { acc[i][0] = 0ull; acc[i][1] = 0ull; }

    for (int kt = 0; kt < CIN; kt += 32) {
#pragma unroll
        for (int j = 0; j < 4; ++j) {
            int f4 = tid + j * 256;
            int r = f4 >> 3;
            int kq = f4 & 7;
            float4 v = make_float4(0.f, 0.f, 0.f, 0.f);
            int gr = row0 + r;
            if (gr < N) v = *(const float4*)(x + (size_t)gr * CIN + kt + kq * 4);
            xs[r][kq * 4 + 0] = v.x; xs[r][kq * 4 + 1] = v.y;
            xs[r][kq * 4 + 2] = v.z; xs[r][kq * 4 + 3] = v.w;
        }
#pragma unroll
        for (int j = 0; j < 4; ++j) {
            int idx = tid + j * 256;   // 0..1023
            int k = idx >> 5;
            int p = idx & 31;
            int gp = cb * 32 + p;
            int gk = kt + k;
            ws[k][p] = make_float2(Wx[gk * H + gp], Wy[gk * H + gp]);
        }
        __syncthreads();
#pragma unroll
        for (int k = 0; k < 32; ++k) {
            const unsigned long long* wp =
                reinterpret_cast<const unsigned long long*>(&ws[k][tx * 2]);
            unsigned long long b0 = wp[0], b1 = wp[1];
#pragma unroll
            for (int i = 0; i < 8; ++i) {
                unsigned long long a2 = pack2(xs[ty * 8 + i][k]);
                ffma2(acc[i][0], a2, b0);
                ffma2(acc[i][1], a2, b1);
            }
        }
        __syncthreads();
    }
    int c0 = cb * 32 + tx * 2;
    float bx0 = bx[c0], by0 = by[c0], bx1 = bx[c0 + 1], by1 = by[c0 + 1];
#pragma unroll
    for (int i = 0; i < 8; ++i) {
        int gr = row0 + ty * 8 + i;
        if (gr < N) {
            float x0, y0, x1, y1;
            unpack2(acc[i][0], x0, y0);
            unpack2(acc[i][1], x1, y1);
            __half2 h0 = __floats2half2_rn(tanhf(x0 + bx0), tanhf(y0 + by0));
            __half2 h1 = __floats2half2_rn(tanhf(x1 + bx1), tanhf(y1 + by1));
            uint2 hv;
            hv.x = *(unsigned int*)&h0;
            hv.y = *(unsigned int*)&h1;
            *(uint2*)(&g_XY0[(size_t)gr * H + c0]) = hv;
        }
    }
}

// ---------------- one LVConv layer ----------------
// warp per dst node. Gather: lanes 0..23 each load the full row slice as ONE
// LDG.128 (uint4 = 4 half2 = 4 channel-pairs), accumulate with HADD2.
// Epilogue: fp32 Euler update from the fp16 state row (1 LDG.128), write one
// uint4 back. fp16-only state: working set 38 MB, fully L2-resident.
__global__ __launch_bounds__(256) void k_layer(
        const uint4* __restrict__ XYin,     // rows of 24 uint4
        uint4* __restrict__ XYout,
        const float* __restrict__ al, const float* __restrict__ be,
        const float* __restrict__ ga, const float* __restrict__ de,
        int N) {
    int w = (blockIdx.x * blockDim.x + threadIdx.x) >> 5;
    int lane = threadIdx.x & 31;
    if (w >= N) return;
    bool act = lane < 24;
    int s0 = __ldg(&g_rowptr[w]);
    int s1 = __ldg(&g_rowptr[w + 1]);

    __half2 acc0 = __floats2half2_rn(0.f, 0.f);
    __half2 acc1 = acc0, acc2 = acc0, acc3 = acc0;

    int e = s0;
    for (; e + 4 <= s1; e += 4) {
        int sA = __ldg(&g_srcs[e + 0]);
        int sB = __ldg(&g_srcs[e + 1]);
        int sC = __ldg(&g_srcs[e + 2]);
        int sD = __ldg(&g_srcs[e + 3]);
        if (act) {
            uint4 vA = __ldg(XYin + (size_t)sA * 24 + lane);
            uint4 vB = __ldg(XYin + (size_t)sB * 24 + lane);
            uint4 vC = __ldg(XYin + (size_t)sC * 24 + lane);
            uint4 vD = __ldg(XYin + (size_t)sD * 24 + lane);
            acc0 = __hadd2(acc0, __hadd2(__hadd2(*(__half2*)&vA.x, *(__half2*)&vB.x),
                                         __hadd2(*(__half2*)&vC.x, *(__half2*)&vD.x)));
            acc1 = __hadd2(acc1, __hadd2(__hadd2(*(__half2*)&vA.y, *(__half2*)&vB.y),
                                         __hadd2(*(__half2*)&vC.y, *(__half2*)&vD.y)));
            acc2 = __hadd2(acc2, __hadd2(__hadd2(*(__half2*)&vA.z, *(__half2*)&vB.z),
                                         __hadd2(*(__half2*)&vC.z, *(__half2*)&vD.z)));
            acc3 = __hadd2(acc3, __hadd2(__hadd2(*(__half2*)&vA.w, *(__half2*)&vB.w),
                                         __hadd2(*(__half2*)&vC.w, *(__half2*)&vD.w)));
        }
    }
    for (; e < s1; ++e) {
        int s = __ldg(&g_srcs[e]);
        if (act) {
            uint4 v = __ldg(XYin + (size_t)s * 24 + lane);
            acc0 = __hadd2(acc0, *(__half2*)&v.x);
            acc1 = __hadd2(acc1, *(__half2*)&v.y);
            acc2 = __hadd2(acc2, *(__half2*)&v.z);
            acc3 = __hadd2(acc3, *(__half2*)&v.w);
        }
    }
    if (!act) return;

    float dinv = __ldg(&g_deginv[w]);
    float2 a0 = __half22float2(acc0);
    float2 a1 = __half22float2(acc1);
    float2 a2 = __half22float2(acc2);
    float2 a3 = __half22float2(acc3);
    float aggX[4] = {a0.x * dinv, a1.x * dinv, a2.x * dinv, a3.x * dinv};
    float aggY[4] = {a0.y * dinv, a1.y * dinv, a2.y * dinv, a3.y * dinv};

    int c0 = lane * 4;
    size_t rbase = (size_t)w * 24 + lane;
    uint4 sv = __ldg(XYin + rbase);
    float2 s0f = __half22float2(*(__half2*)&sv.x);
    float2 s1f = __half22float2(*(__half2*)&sv.y);
    float2 s2f = __half22float2(*(__half2*)&sv.z);
    float2 s3f = __half22float2(*(__half2*)&sv.w);

    float4 alv = *(const float4*)(al + c0);
    float4 bev = *(const float4*)(be + c0);
    float4 gav = *(const float4*)(ga + c0);
    float4 dev = *(const float4*)(de + c0);

    float Xn0 = s0f.x + DTC * s0f.x * (alv.x - bev.x * aggY[0]);
    float Yn0 = s0f.y + DTC * s0f.y * (-gav.x + dev.x * aggX[0]);
    float Xn1 = s1f.x + DTC * s1f.x * (alv.y - bev.y * aggY[1]);
    float Yn1 = s1f.y + DTC * s1f.y * (-gav.y + dev.y * aggX[1]);
    float Xn2 = s2f.x + DTC * s2f.x * (alv.z - bev.z * aggY[2]);
    float Yn2 = s2f.y + DTC * s2f.y * (-gav.z + dev.z * aggX[2]);
    float Xn3 = s3f.x + DTC * s3f.x * (alv.w - bev.w * aggY[3]);
    float Yn3 = s3f.y + DTC * s3f.y * (-gav.w + dev.w * aggX[3]);

    __half2 h0 = __floats2half2_rn(Xn0, Yn0);
    __half2 h1 = __floats2half2_rn(Xn1, Yn1);
    __half2 h2 = __floats2half2_rn(Xn2, Yn2);
    __half2 h3 = __floats2half2_rn(Xn3, Yn3);
    uint4 hv;
    hv.x = *(unsigned int*)&h0; hv.y = *(unsigned int*)&h1;
    hv.z = *(unsigned int*)&h2; hv.w = *(unsigned int*)&h3;
    XYout[rbase] = hv;
}

// ---------------- readout: out = [X|Y] @ Wr + br, from fp16 interleaved ----
__global__ __launch_bounds__(128) void k_readout(
        const uint4* __restrict__ XY,       // rows of 24 uint4
        const float* __restrict__ Wr, const float* __restrict__ br,
        float* __restrict__ out, int N) {
    __shared__ float2 xs2[128][33];
    __shared__ float  wsX[32][COUT];
    __shared__ float  wsY[32][COUT];
    int tid = threadIdx.x;
    int tx = tid & 7;
    int ty = tid >> 3;
    int row0 = blockIdx.x * 128;
    float acc[8][5];
#pragma unroll
    for (int i = 0; i < 8; ++i)
#pragma unroll
        for (int j = 0; j < 5; ++j) acc[i][j] = 0.f;

    for (int kt = 0; kt < H; kt += 32) {
        // 128 rows x 32 channels (half2) = 128 x 8 uint4 -> 8 per thread
#pragma unroll
        for (int j = 0; j < 8; ++j) {
            int u4 = tid + j * 128;
            int r = u4 >> 3;
            int q = u4 & 7;           // uint4 index within the 32-ch chunk
            int gr = row0 + r;
            uint4 v = make_uint4(0u, 0u, 0u, 0u);
            if (gr < N) v = __ldg(XY + (size_t)gr * 24 + (kt >> 2) + q);
            int cc = q * 4;
            xs2[r][cc + 0] = __half22float2(*(__half2*)&v.x);
            xs2[r][cc + 1] = __half22float2(*(__half2*)&v.y);
            xs2[r][cc + 2] = __half22float2(*(__half2*)&v.z);
            xs2[r][cc + 3] = __half22float2(*(__half2*)&v.w);
        }
#pragma unroll
        for (int j = 0; j < 10; ++j) {
            int idx = tid + j * 128;
            if (idx < 32 * COUT) {
                int k = idx / COUT;
                int c = idx - k * COUT;
                wsX[k][c] = Wr[(size_t)(kt + k) * COUT + c];
                wsY[k][c] = Wr[(size_t)(H + kt + k) * COUT + c];
            }
        }
        __syncthreads();
#pragma unroll
        for (int k = 0; k < 32; ++k) {
            float2 xv[8];
#pragma unroll
            for (int i = 0; i < 8; ++i) xv[i] = xs2[ty * 8 + i][k];
            float wx[5], wy[5];
#pragma unroll
            for (int j = 0; j < 5; ++j) { wx[j] = wsX[k][tx * 5 + j]; wy[j] = wsY[k][tx * 5 + j]; }
#pragma unroll
            for (int i = 0; i < 8; ++i)
#pragma unroll
                for (int j = 0; j < 5; ++j)
                    acc[i][j] += xv[i].x * wx[j] + xv[i].y * wy[j];
        }
        __syncthreads();
    }
#pragma unroll
    for (int i = 0; i < 8; ++i) {
        int gr = row0 + ty * 8 + i;
        if (gr < N) {
#pragma unroll
            for (int j = 0; j < 5; ++j)
                out[(size_t)gr * COUT + tx * 5 + j] = acc[i][j] + br[tx * 5 + j];
        }
    }
}

// ---------------- launch ----------------
extern "C" void kernel_launch(void* const* d_in, const int* in_sizes, int n_in,
                              void* d_out, int out_size) {
    const float* x  = (const float*)d_in[0];
    const int*   ei = (const int*)d_in[1];
    const float* Wx = (const float*)d_in[2];
    const float* bx = (const float*)d_in[3];
    const float* Wy = (const float*)d_in[4];
    const float* by = (const float*)d_in[5];
    const float* al = (const float*)d_in[6];
    const float* be = (const float*)d_in[7];
    const float* ga = (const float*)d_in[8];
    const float* de = (const float*)d_in[9];
    const float* Wr = (const float*)d_in[10];
    const float* br = (const float*)d_in[11];
    float* out = (float*)d_out;

    int N = in_sizes[0] / CIN;
    int E = in_sizes[1] / 2;
    if (N > NMAX) N = NMAX;
    if (E > EMAX) E = EMAX;
    const int* srcp = ei;
    const int* dstp = ei + E;

    void* degp;
    cudaGetSymbolAddress(&degp, g_deg);
    cudaMemsetAsync(degp, 0, (size_t)N * sizeof(int));

    k_deg<<<(E + 255) / 256, 256>>>(dstp, E);
    k_scan<<<1, 1024>>>(N);
    k_scatter<<<(E + 255) / 256, 256>>>(srcp, dstp, E);

    dim3 gl((N + 127) / 128, 3);
    k_lift<<<gl, 256>>>(x, Wx, bx, Wy, by, N);

    uint4* XYb[2];
    cudaGetSymbolAddress((void**)&XYb[0], g_XY0);
    cudaGetSymbolAddress((void**)&XYb[1], g_XY1);

    int layerBlocks = (N * 32 + 255) / 256;
    for (int l = 0; l < NLAYER; ++l) {
        k_layer<<<layerBlocks, 256>>>(XYb[l & 1], XYb[(l + 1) & 1],
                                      al + l * H, be + l * H, ga + l * H, de + l * H, N);
    }
    k_readout<<<(N + 127) / 128, 128>>>(XYb[NLAYER & 1], Wr, br, out, N);
}